// round 10
// baseline (speedup 1.0000x reference)
#include <cuda_runtime.h>
#include <cuda_fp16.h>
#include <cstdint>
#include <math.h>

// ModulatedConv2D via mma.sync (fp16 split: w_hi*(x_hi+x_lo)) implicit GEMM.
// y = sigma[b,o] * conv2d_same(x * style[b,i], GAIN*weight)
// x[16,512,32,32], style[16,512], weight[512,512,3,3] -> out[16,512,32,32]
// CTA tile: M=256 oc x N=128 pix (512 thr) to amortize the A-tile build.

#define NB 16
#define NC 512
#define HW2 1024
#define EPSV 1e-8f
#define NCHUNK 144   // 16 ic-chunks * 9 taps, K=32 each

static __device__ float g_wsq[NC * NC];
static __device__ float g_sigma[NB * NC];
// weight tiles (hi fp16): [oct2(2)][chunk(144)] -> [256 oc][32 k] fp16 = 16KB
static __device__ unsigned char g_btiles[(size_t)2 * NCHUNK * 16384];

// ---------------------------------------------------------------------------
__device__ __forceinline__ uint32_t smem_u32(const void* p) {
    uint32_t a;
    asm("{ .reg .u64 t; cvta.to.shared.u64 t, %1; cvt.u32.u64 %0, t; }"
        : "=r"(a) : "l"(p));
    return a;
}
#define CP_ASYNC16(dst, src) \
    asm volatile("cp.async.cg.shared.global [%0], [%1], 16;" :: "r"(dst), "l"(src))
#define CP_COMMIT() asm volatile("cp.async.commit_group;")
#define CP_WAIT0()  asm volatile("cp.async.wait_group 0;" ::: "memory")

#define LDMX4(r, addr) \
    asm volatile("ldmatrix.sync.aligned.m8n8.x4.shared.b16 {%0,%1,%2,%3}, [%4];" \
                 : "=r"((r)[0]), "=r"((r)[1]), "=r"((r)[2]), "=r"((r)[3]) : "r"(addr))
#define LDMX2(r, addr) \
    asm volatile("ldmatrix.sync.aligned.m8n8.x2.shared.b16 {%0,%1}, [%2];" \
                 : "=r"((r)[0]), "=r"((r)[1]) : "r"(addr))

#define MMA16816(d, a, b) \
    asm volatile("mma.sync.aligned.m16n8k16.row.col.f32.f16.f16.f32 " \
                 "{%0,%1,%2,%3}, {%4,%5,%6,%7}, {%8,%9}, {%0,%1,%2,%3};" \
                 : "+f"((d)[0]), "+f"((d)[1]), "+f"((d)[2]), "+f"((d)[3]) \
                 : "r"((a)[0]), "r"((a)[1]), "r"((a)[2]), "r"((a)[3]), \
                   "r"((b)[0]), "r"((b)[1]))

// ---------------------------------------------------------------------------
// wsq[oc,ic] = sum_k (GAIN*w)^2
// ---------------------------------------------------------------------------
__global__ void wsq_kernel(const float* __restrict__ weight, float gain) {
    const int oc0 = blockIdx.x * 64;
    const int ic0 = blockIdx.y * 8;
    __shared__ float sw[64][73];
    for (int idx = threadIdx.x; idx < 64 * 72; idx += 256) {
        int o = idx / 72, ik = idx % 72;
        sw[o][ik] = weight[(size_t)(oc0 + o) * 4608 + ic0 * 9 + ik] * gain;
    }
    __syncthreads();
    for (int idx = threadIdx.x; idx < 64 * 8; idx += 256) {
        int o = idx >> 3, i = idx & 7;
        float s = 0.f;
#pragma unroll
        for (int k = 0; k < 9; ++k) { float v = sw[o][i * 9 + k]; s += v * v; }
        g_wsq[(oc0 + o) * NC + ic0 + i] = s;
    }
}

__global__ void sigma_kernel(const float* __restrict__ style) {
    const int b = blockIdx.y;
    const int warp = threadIdx.x >> 5, lane = threadIdx.x & 31;
    const int oc = blockIdx.x * 8 + warp;
    float v = 0.f;
    for (int i = lane; i < NC; i += 32) {
        float s = style[b * NC + i];
        v += s * s * g_wsq[oc * NC + i];
    }
#pragma unroll
    for (int off = 16; off; off >>= 1) v += __shfl_xor_sync(0xffffffffu, v, off);
    if (lane == 0) g_sigma[b * NC + oc] = rsqrtf(v + EPSV);
}

// ---------------------------------------------------------------------------
// prep: weights -> hi fp16 tiles. Block layout: [oct2][chunk] -> 256 rows x 64B.
// grid (144, 4), 256 threads: thread = (oc 0..127 within 128-grp) x (khalf 0..1)
// ---------------------------------------------------------------------------
__global__ void prep_b(const float* __restrict__ weight, float gain) {
    const int cc = blockIdx.x, og = blockIdx.y;     // og: 128-oc group 0..3
    const int icch = cc / 9, tap = cc % 9;
    const int ocl = threadIdx.x >> 1;
    const int kh = (threadIdx.x & 1) * 16;
    const int oc = og * 128 + ocl;
    const float* wr = weight + (size_t)oc * 4608 + (size_t)(icch * 32 + kh) * 9 + tap;
    union { __half2 h2[8]; uint4 u4[2]; } H;
#pragma unroll
    for (int j = 0; j < 8; ++j) {
        float v0 = wr[(2 * j) * 9] * gain;
        float v1 = wr[(2 * j + 1) * 9] * gain;
        H.h2[j] = __halves2half2(__float2half(v0), __float2half(v1));
    }
    unsigned char* blk = g_btiles + (size_t)((og >> 1) * NCHUNK + cc) * 16384;
    const int row = (og & 1) * 128 + ocl;   // row within 256-oc block
    uint4* dh = (uint4*)(blk + row * 64 + kh * 2);
    dh[0] = H.u4[0]; dh[1] = H.u4[1];
}

// ---------------------------------------------------------------------------
// conv: grid (8 pixtiles, 2 octiles, 16 b), 512 threads (16 warps).
// CTA tile: M=256 oc x N=128 pix, K-chunk 32.
// smem stage (40960B): WH[256][40]h 20480 | XH 10240 | XL 10240
// stages at 0 / 40960 ; s_sig @81920 (1024B) ; s_sty @82944 (2048B)
// ---------------------------------------------------------------------------
#define RS 80u          // row stride bytes (40 halves)
#define ST_WH 0u
#define ST_XH 20480u
#define ST_XL 30720u
#define STAGE 40960u
#define SM_TOTAL 84992

__global__ void __launch_bounds__(512, 1)
conv_mma(const float* __restrict__ x, const float* __restrict__ style,
         float* __restrict__ out) {
    extern __shared__ char smem[];
    const uint32_t sb = smem_u32(smem);
    const int tid = threadIdx.x;
    const int lane = tid & 31, wid = tid >> 5;
    const int wm = wid & 3;        // m warp (oc): 0..3 -> offset wm*64
    const int wn = wid >> 2;       // n warp (pix): 0..3 -> offset wn*32
    const int pixtile = blockIdx.x, octile = blockIdx.y, b = blockIdx.z;

    float* s_sig = (float*)(smem + 81920);
    float* s_sty = (float*)(smem + 82944);
    for (int i = tid; i < 256; i += 512) s_sig[i] = g_sigma[b * NC + octile * 256 + i];
    for (int i = tid; i < NC; i += 512) s_sty[i] = style[b * NC + i];
    __syncthreads();   // s_sty must be visible to all warps before prologue storeX

    const float* xb = x + (size_t)b * NC * HW2;
    const unsigned char* wbase = g_btiles + (size_t)octile * NCHUNK * 16384;

    // per-thread build coords: p = pixel (0..127), khf = k quarter (0/8/16/24)
    const int p = tid >> 2;
    const int khf = (tid & 3) * 8;
    const int pr = pixtile * 4 + (p >> 5);   // image row of this pixel
    const int pc = p & 31;                   // image col

    // ldmatrix per-lane offsets
    const uint32_t aoff = (uint32_t)(lane & 15) * RS + (uint32_t)(lane >> 4) * 16u;
    const uint32_t boff = (uint32_t)(lane & 7) * RS + (uint32_t)((lane >> 3) & 1) * 16u;

    float acc[4][4][4];
#pragma unroll
    for (int m = 0; m < 4; ++m)
#pragma unroll
        for (int n = 0; n < 4; ++n)
#pragma unroll
            for (int r = 0; r < 4; ++r) acc[m][n][r] = 0.f;

    // ---- helpers ----
    auto issueW = [&](int c, uint32_t stb) {
        const unsigned char* src = wbase + (size_t)c * 16384;
#pragma unroll
        for (int j = 0; j < 2; ++j) {
            int cidx = tid + j * 512;               // 0..1023 16B chunks
            int row = cidx >> 2, off = cidx & 3;
            CP_ASYNC16(sb + stb + ST_WH + row * RS + off * 16, src + cidx * 16);
        }
        CP_COMMIT();
    };
    auto prefX = [&](int c, float* xv) {
        const int icch = c / 9, tap = c - icch * 9;
        const int sr = pr + tap / 3 - 1, sc = pc + tap % 3 - 1;
        const bool inb = ((unsigned)sr < 32u) && ((unsigned)sc < 32u);
        const float* xp = xb + ((size_t)(icch * 32 + khf) << 10) +
                          (inb ? (sr * 32 + sc) : 0);
#pragma unroll
        for (int j = 0; j < 8; ++j) xv[j] = inb ? xp[(size_t)j << 10] : 0.f;
    };
    auto storeX = [&](int c, uint32_t stb, const float* xv) {
        const int icch = c / 9;
        const int styb = icch * 32 + khf;
        union { __half2 h2[4]; uint4 u4; } H, L;
#pragma unroll
        for (int j = 0; j < 4; ++j) {
            float v0 = xv[2 * j] * s_sty[styb + 2 * j];
            float v1 = xv[2 * j + 1] * s_sty[styb + 2 * j + 1];
            __half h0 = __float2half(v0), h1 = __float2half(v1);
            __half l0 = __float2half(v0 - __half2float(h0));
            __half l1 = __float2half(v1 - __half2float(h1));
            H.h2[j] = __halves2half2(h0, h1);
            L.h2[j] = __halves2half2(l0, l1);
        }
        *(uint4*)(smem + stb + ST_XH + p * RS + khf * 2) = H.u4;
        *(uint4*)(smem + stb + ST_XL + p * RS + khf * 2) = L.u4;
    };
    // one K=32 subtile of MMAs on stage stb (kb = 0 or 32 bytes)
    auto mmaKS = [&](uint32_t stb, uint32_t kb) {
        uint32_t ah[4][4], bh[4][2], bl[4][2];
#pragma unroll
        for (int m = 0; m < 4; ++m)
            LDMX4(ah[m], sb + stb + ST_WH + (uint32_t)(wm * 64 + m * 16) * RS + kb + aoff);
#pragma unroll
        for (int n = 0; n < 4; ++n)
            LDMX2(bh[n], sb + stb + ST_XH + (uint32_t)(wn * 32 + n * 8) * RS + kb + boff);
#pragma unroll
        for (int m = 0; m < 4; ++m)
#pragma unroll
            for (int n = 0; n < 4; ++n) MMA16816(acc[m][n], ah[m], bh[n]);
#pragma unroll
        for (int n = 0; n < 4; ++n)
            LDMX2(bl[n], sb + stb + ST_XL + (uint32_t)(wn * 32 + n * 8) * RS + kb + boff);
#pragma unroll
        for (int m = 0; m < 4; ++m)
#pragma unroll
            for (int n = 0; n < 4; ++n) MMA16816(acc[m][n], ah[m], bl[n]);
    };

    // ---- prologue: chunk 0 ----
    {
        issueW(0, 0);
        float xv[8];
        prefX(0, xv);
        storeX(0, 0, xv);
        CP_WAIT0();
        __syncthreads();
    }

    // ---- main loop ----
#pragma unroll 1
    for (int c = 0; c < NCHUNK; ++c) {
        const uint32_t stb = (uint32_t)(c & 1) * STAGE;
        const uint32_t nstb = stb ^ STAGE;
        const bool more = (c + 1 < NCHUNK);
        float xv[8];
        if (more) {
            issueW(c + 1, nstb);
            prefX(c + 1, xv);
        }
        mmaKS(stb, 0u);                 // K sub-tile 0 (hides LDG latency)
        if (more) storeX(c + 1, nstb, xv);  // STS/convert overlaps tensor pipe
        mmaKS(stb, 32u);                // K sub-tile 1
        if (more) CP_WAIT0();
        __syncthreads();
    }

    // ---- epilogue: demodulate + store ----
    float* ob = out + (size_t)b * NC * HW2 + (size_t)octile * 256 * HW2 +
                pixtile * 128;
#pragma unroll
    for (int m = 0; m < 4; ++m) {
        const int r0 = wm * 64 + m * 16 + (lane >> 2);
        const float sg0 = s_sig[r0], sg1 = s_sig[r0 + 8];
#pragma unroll
        for (int n = 0; n < 4; ++n) {
            const int col = wn * 32 + n * 8 + (lane & 3) * 2;
            float2 v0 = make_float2(acc[m][n][0] * sg0, acc[m][n][1] * sg0);
            float2 v1 = make_float2(acc[m][n][2] * sg1, acc[m][n][3] * sg1);
            *(float2*)(ob + (size_t)r0 * HW2 + col) = v0;
            *(float2*)(ob + (size_t)(r0 + 8) * HW2 + col) = v1;
        }
    }
}

// ---------------------------------------------------------------------------
extern "C" void kernel_launch(void* const* d_in, const int* in_sizes, int n_in,
                              void* d_out, int out_size) {
    const float* x      = (const float*)d_in[0];
    const float* style  = (const float*)d_in[1];
    const float* weight = (const float*)d_in[2];
    float* out          = (float*)d_out;
    (void)in_sizes; (void)n_in; (void)out_size;

    const float gain = 1.0f / sqrtf(4608.0f);

    cudaFuncSetAttribute(conv_mma, cudaFuncAttributeMaxDynamicSharedMemorySize,
                         SM_TOTAL);

    wsq_kernel<<<dim3(8, 64), 256>>>(weight, gain);
    prep_b<<<dim3(NCHUNK, 4), 256>>>(weight, gain);
    sigma_kernel<<<dim3(64, 16), 256>>>(style);
    conv_mma<<<dim3(8, 2, 16), 512, SM_TOTAL>>>(x, style, out);
}

// round 11
// speedup vs baseline: 1.4744x; 1.4744x over previous
#include <cuda_runtime.h>
#include <cuda_fp16.h>
#include <cstdint>
#include <math.h>

// ModulatedConv2D via mma.sync (pure fp16 operands, fp32 accum) implicit GEMM.
// y = sigma[b,o] * conv2d_same(x * style[b,i], GAIN*weight)
// x[16,512,32,32], style[16,512], weight[512,512,3,3] -> out[16,512,32,32]

#define NB 16
#define NC 512
#define HW2 1024
#define EPSV 1e-8f
#define NCHUNK 144   // 16 ic-chunks * 9 taps, K=32 each

static __device__ float g_wsq[NC * NC];
static __device__ float g_sigma[NB * NC];
// weight tiles (hi fp16): [octile(4)][chunk(144)] -> [128 oc][32 k] fp16 (8KB)
static __device__ unsigned char g_btiles[(size_t)4 * NCHUNK * 8192];

// ---------------------------------------------------------------------------
__device__ __forceinline__ uint32_t smem_u32(const void* p) {
    uint32_t a;
    asm("{ .reg .u64 t; cvta.to.shared.u64 t, %1; cvt.u32.u64 %0, t; }"
        : "=r"(a) : "l"(p));
    return a;
}
#define CP_ASYNC16(dst, src) \
    asm volatile("cp.async.cg.shared.global [%0], [%1], 16;" :: "r"(dst), "l"(src))
#define CP_COMMIT() asm volatile("cp.async.commit_group;")
#define CP_WAIT0()  asm volatile("cp.async.wait_group 0;" ::: "memory")

#define LDMX4(r, addr) \
    asm volatile("ldmatrix.sync.aligned.m8n8.x4.shared.b16 {%0,%1,%2,%3}, [%4];" \
                 : "=r"((r)[0]), "=r"((r)[1]), "=r"((r)[2]), "=r"((r)[3]) : "r"(addr))
#define LDMX2(r, addr) \
    asm volatile("ldmatrix.sync.aligned.m8n8.x2.shared.b16 {%0,%1}, [%2];" \
                 : "=r"((r)[0]), "=r"((r)[1]) : "r"(addr))

#define MMA16816(d, a, b) \
    asm volatile("mma.sync.aligned.m16n8k16.row.col.f32.f16.f16.f32 " \
                 "{%0,%1,%2,%3}, {%4,%5,%6,%7}, {%8,%9}, {%0,%1,%2,%3};" \
                 : "+f"((d)[0]), "+f"((d)[1]), "+f"((d)[2]), "+f"((d)[3]) \
                 : "r"((a)[0]), "r"((a)[1]), "r"((a)[2]), "r"((a)[3]), \
                   "r"((b)[0]), "r"((b)[1]))

// ---------------------------------------------------------------------------
// wsq[oc,ic] = sum_k (GAIN*w)^2
// ---------------------------------------------------------------------------
__global__ void wsq_kernel(const float* __restrict__ weight, float gain) {
    const int oc0 = blockIdx.x * 64;
    const int ic0 = blockIdx.y * 8;
    __shared__ float sw[64][73];
    for (int idx = threadIdx.x; idx < 64 * 72; idx += 256) {
        int o = idx / 72, ik = idx % 72;
        sw[o][ik] = weight[(size_t)(oc0 + o) * 4608 + ic0 * 9 + ik] * gain;
    }
    __syncthreads();
    for (int idx = threadIdx.x; idx < 64 * 8; idx += 256) {
        int o = idx >> 3, i = idx & 7;
        float s = 0.f;
#pragma unroll
        for (int k = 0; k < 9; ++k) { float v = sw[o][i * 9 + k]; s += v * v; }
        g_wsq[(oc0 + o) * NC + ic0 + i] = s;
    }
}

__global__ void sigma_kernel(const float* __restrict__ style) {
    const int b = blockIdx.y;
    const int warp = threadIdx.x >> 5, lane = threadIdx.x & 31;
    const int oc = blockIdx.x * 8 + warp;
    float v = 0.f;
    for (int i = lane; i < NC; i += 32) {
        float s = style[b * NC + i];
        v += s * s * g_wsq[oc * NC + i];
    }
#pragma unroll
    for (int off = 16; off; off >>= 1) v += __shfl_xor_sync(0xffffffffu, v, off);
    if (lane == 0) g_sigma[b * NC + oc] = rsqrtf(v + EPSV);
}

// ---------------------------------------------------------------------------
// prep: weights -> hi fp16 tiles, layout [oc(128)][k(32)] packed 64B rows.
// grid (144, 4), 256 threads: thread = (oc 0..127) x (khalf 0..1)
// ---------------------------------------------------------------------------
__global__ void prep_b(const float* __restrict__ weight, float gain) {
    const int cc = blockIdx.x, octile = blockIdx.y;
    const int icch = cc / 9, tap = cc % 9;
    const int ocl = threadIdx.x >> 1;
    const int kh = (threadIdx.x & 1) * 16;
    const int oc = octile * 128 + ocl;
    const float* wr = weight + (size_t)oc * 4608 + (size_t)(icch * 32 + kh) * 9 + tap;
    union { __half2 h2[8]; uint4 u4[2]; } H;
#pragma unroll
    for (int j = 0; j < 8; ++j) {
        float v0 = wr[(2 * j) * 9] * gain;
        float v1 = wr[(2 * j + 1) * 9] * gain;
        H.h2[j] = __halves2half2(__float2half(v0), __float2half(v1));
    }
    unsigned char* blk = g_btiles + (size_t)(octile * NCHUNK + cc) * 8192;
    uint4* dh = (uint4*)(blk + ocl * 64 + kh * 2);
    dh[0] = H.u4[0]; dh[1] = H.u4[1];
}

// ---------------------------------------------------------------------------
// conv: grid (8 pixtiles, 4 octiles, 16 b), 256 threads (8 warps).
// CTA tile: M=128 oc x N=128 pix, K-chunk 32. Pure fp16 operands.
// smem stage (20480B): WH[128][40]h 10240 | XH 10240
// stages at 0 / 20480 ; s_sig @40960 (512B) ; s_sty @41472 (2048B)
// ---------------------------------------------------------------------------
#define RS 80u          // row stride bytes (40 halves)
#define ST_WH 0u
#define ST_XH 10240u
#define STAGE 20480u
#define SM_TOTAL 43520

__global__ void __launch_bounds__(256, 2)
conv_mma(const float* __restrict__ x, const float* __restrict__ style,
         float* __restrict__ out) {
    extern __shared__ char smem[];
    const uint32_t sb = smem_u32(smem);
    const int tid = threadIdx.x;
    const int lane = tid & 31, wid = tid >> 5;
    const int wm = wid & 1;        // m warp (oc): 0..1 -> offset wm*64
    const int wn = wid >> 1;       // n warp (pix): 0..3 -> offset wn*32
    const int pixtile = blockIdx.x, octile = blockIdx.y, b = blockIdx.z;

    float* s_sig = (float*)(smem + 40960);
    float* s_sty = (float*)(smem + 41472);
    for (int i = tid; i < 128; i += 256) s_sig[i] = g_sigma[b * NC + octile * 128 + i];
    for (int i = tid; i < NC; i += 256) s_sty[i] = style[b * NC + i];
    __syncthreads();   // s_sty must be visible to all warps before prologue storeX

    const float* xb = x + (size_t)b * NC * HW2;
    const unsigned char* wbase = g_btiles + (size_t)octile * NCHUNK * 8192;

    // per-thread build coords: p = pixel row in tile, khf = k half (0/16)
    const int p = tid >> 1;
    const int khf = (tid & 1) * 16;
    const int pr = pixtile * 4 + (p >> 5);   // image row of this pixel
    const int pc = p & 31;                   // image col

    // ldmatrix per-lane offsets
    const uint32_t aoff = (uint32_t)(lane & 15) * RS + (uint32_t)(lane >> 4) * 16u;
    const uint32_t boff = (uint32_t)(lane & 7) * RS + (uint32_t)((lane >> 3) & 1) * 16u;

    float acc[4][4][4];
#pragma unroll
    for (int m = 0; m < 4; ++m)
#pragma unroll
        for (int n = 0; n < 4; ++n)
#pragma unroll
            for (int r = 0; r < 4; ++r) acc[m][n][r] = 0.f;

    // ---- helpers ----
    auto issueW = [&](int c, uint32_t stb) {
        const unsigned char* src = wbase + (size_t)c * 8192;
#pragma unroll
        for (int j = 0; j < 2; ++j) {
            int cidx = tid + j * 256;               // 0..511 16B chunks
            int row = cidx >> 2, off = cidx & 3;
            CP_ASYNC16(sb + stb + ST_WH + row * RS + off * 16, src + cidx * 16);
        }
        CP_COMMIT();
    };
    auto prefX = [&](int c, float* xv) {
        const int icch = c / 9, tap = c - icch * 9;
        const int sr = pr + tap / 3 - 1, sc = pc + tap % 3 - 1;
        const bool inb = ((unsigned)sr < 32u) && ((unsigned)sc < 32u);
        const float* xp = xb + ((size_t)(icch * 32 + khf) << 10) +
                          (inb ? (sr * 32 + sc) : 0);
#pragma unroll
        for (int j = 0; j < 16; ++j) xv[j] = inb ? xp[(size_t)j << 10] : 0.f;
    };
    auto storeX = [&](int c, uint32_t stb, const float* xv) {
        const int icch = c / 9;
        const int styb = icch * 32 + khf;
        union { __half2 h2[8]; uint4 u4[2]; } H;
#pragma unroll
        for (int j = 0; j < 8; ++j) {
            float v0 = xv[2 * j] * s_sty[styb + 2 * j];
            float v1 = xv[2 * j + 1] * s_sty[styb + 2 * j + 1];
            H.h2[j] = __halves2half2(__float2half(v0), __float2half(v1));
        }
        uint4* dh = (uint4*)(smem + stb + ST_XH + p * RS + khf * 2);
        dh[0] = H.u4[0]; dh[1] = H.u4[1];
    };
    // one K=32 subtile of MMAs on stage stb (kb = 0 or 32 bytes)
    auto mmaKS = [&](uint32_t stb, uint32_t kb) {
        uint32_t ah[4][4], bh[4][2];
#pragma unroll
        for (int m = 0; m < 4; ++m)
            LDMX4(ah[m], sb + stb + ST_WH + (uint32_t)(wm * 64 + m * 16) * RS + kb + aoff);
#pragma unroll
        for (int n = 0; n < 4; ++n)
            LDMX2(bh[n], sb + stb + ST_XH + (uint32_t)(wn * 32 + n * 8) * RS + kb + boff);
#pragma unroll
        for (int m = 0; m < 4; ++m)
#pragma unroll
            for (int n = 0; n < 4; ++n) MMA16816(acc[m][n], ah[m], bh[n]);
    };

    // ---- prologue: chunk 0 ----
    {
        issueW(0, 0);
        float xv[16];
        prefX(0, xv);
        storeX(0, 0, xv);
        CP_WAIT0();
        __syncthreads();
    }

    // ---- main loop ----
#pragma unroll 1
    for (int c = 0; c < NCHUNK; ++c) {
        const uint32_t stb = (uint32_t)(c & 1) * STAGE;
        const uint32_t nstb = stb ^ STAGE;
        const bool more = (c + 1 < NCHUNK);
        float xv[16];
        if (more) {
            issueW(c + 1, nstb);
            prefX(c + 1, xv);
        }
        mmaKS(stb, 0u);                 // K sub-tile 0 (hides LDG latency)
        if (more) storeX(c + 1, nstb, xv);  // STS/convert overlaps tensor pipe
        mmaKS(stb, 32u);                // K sub-tile 1
        if (more) CP_WAIT0();
        __syncthreads();
    }

    // ---- epilogue: demodulate + store ----
    float* ob = out + (size_t)b * NC * HW2 + (size_t)octile * 128 * HW2 +
                pixtile * 128;
#pragma unroll
    for (int m = 0; m < 4; ++m) {
        const int r0 = wm * 64 + m * 16 + (lane >> 2);
        const float sg0 = s_sig[r0], sg1 = s_sig[r0 + 8];
#pragma unroll
        for (int n = 0; n < 4; ++n) {
            const int col = wn * 32 + n * 8 + (lane & 3) * 2;
            float2 v0 = make_float2(acc[m][n][0] * sg0, acc[m][n][1] * sg0);
            float2 v1 = make_float2(acc[m][n][2] * sg1, acc[m][n][3] * sg1);
            *(float2*)(ob + (size_t)r0 * HW2 + col) = v0;
            *(float2*)(ob + (size_t)(r0 + 8) * HW2 + col) = v1;
        }
    }
}

// ---------------------------------------------------------------------------
extern "C" void kernel_launch(void* const* d_in, const int* in_sizes, int n_in,
                              void* d_out, int out_size) {
    const float* x      = (const float*)d_in[0];
    const float* style  = (const float*)d_in[1];
    const float* weight = (const float*)d_in[2];
    float* out          = (float*)d_out;
    (void)in_sizes; (void)n_in; (void)out_size;

    const float gain = 1.0f / sqrtf(4608.0f);

    cudaFuncSetAttribute(conv_mma, cudaFuncAttributeMaxDynamicSharedMemorySize,
                         SM_TOTAL);

    wsq_kernel<<<dim3(8, 64), 256>>>(weight, gain);
    prep_b<<<dim3(NCHUNK, 4), 256>>>(weight, gain);
    sigma_kernel<<<dim3(64, 16), 256>>>(style);
    conv_mma<<<dim3(8, 4, 16), 256, SM_TOTAL>>>(x, style, out);
}

// round 12
// speedup vs baseline: 1.9517x; 1.3237x over previous
#include <cuda_runtime.h>
#include <cuda_fp16.h>
#include <cstdint>
#include <math.h>

// ModulatedConv2D via mma.sync (pure fp16 operands, fp32 accum) implicit GEMM.
// y = sigma[b,o] * conv2d_same(x * style[b,i], GAIN*weight)
// x[16,512,32,32], style[16,512], weight[512,512,3,3] -> out[16,512,32,32]
// R12: X stored once per ic-chunk as an image-space halo tile (6x34 pixels,
// zero-padded); the 9 conv taps become ldmatrix address offsets.

#define NB 16
#define NC 512
#define HW2 1024
#define EPSV 1e-8f
#define NCHUNK 144   // 16 ic-chunks * 9 taps, K=32 each

static __device__ float g_wsq[NC * NC];
static __device__ float g_sigma[NB * NC];
// weight tiles fp16: [octile(4)][chunk(144)] -> [128 oc][32 k] (8KB)
static __device__ unsigned char g_btiles[(size_t)4 * NCHUNK * 8192];

// ---------------------------------------------------------------------------
__device__ __forceinline__ uint32_t smem_u32(const void* p) {
    uint32_t a;
    asm("{ .reg .u64 t; cvta.to.shared.u64 t, %1; cvt.u32.u64 %0, t; }"
        : "=r"(a) : "l"(p));
    return a;
}
#define CP_ASYNC16(dst, src) \
    asm volatile("cp.async.cg.shared.global [%0], [%1], 16;" :: "r"(dst), "l"(src))
#define CP_COMMIT() asm volatile("cp.async.commit_group;")
#define CP_WAIT0()  asm volatile("cp.async.wait_group 0;" ::: "memory")

#define LDMX4(r, addr) \
    asm volatile("ldmatrix.sync.aligned.m8n8.x4.shared.b16 {%0,%1,%2,%3}, [%4];" \
                 : "=r"((r)[0]), "=r"((r)[1]), "=r"((r)[2]), "=r"((r)[3]) : "r"(addr))
#define LDMX2(r, addr) \
    asm volatile("ldmatrix.sync.aligned.m8n8.x2.shared.b16 {%0,%1}, [%2];" \
                 : "=r"((r)[0]), "=r"((r)[1]) : "r"(addr))

#define MMA16816(d, a, b) \
    asm volatile("mma.sync.aligned.m16n8k16.row.col.f32.f16.f16.f32 " \
                 "{%0,%1,%2,%3}, {%4,%5,%6,%7}, {%8,%9}, {%0,%1,%2,%3};" \
                 : "+f"((d)[0]), "+f"((d)[1]), "+f"((d)[2]), "+f"((d)[3]) \
                 : "r"((a)[0]), "r"((a)[1]), "r"((a)[2]), "r"((a)[3]), \
                   "r"((b)[0]), "r"((b)[1]))

// ---------------------------------------------------------------------------
// wsq[oc,ic] = sum_k (GAIN*w)^2
// ---------------------------------------------------------------------------
__global__ void wsq_kernel(const float* __restrict__ weight, float gain) {
    const int oc0 = blockIdx.x * 64;
    const int ic0 = blockIdx.y * 8;
    __shared__ float sw[64][73];
    for (int idx = threadIdx.x; idx < 64 * 72; idx += 256) {
        int o = idx / 72, ik = idx % 72;
        sw[o][ik] = weight[(size_t)(oc0 + o) * 4608 + ic0 * 9 + ik] * gain;
    }
    __syncthreads();
    for (int idx = threadIdx.x; idx < 64 * 8; idx += 256) {
        int o = idx >> 3, i = idx & 7;
        float s = 0.f;
#pragma unroll
        for (int k = 0; k < 9; ++k) { float v = sw[o][i * 9 + k]; s += v * v; }
        g_wsq[(oc0 + o) * NC + ic0 + i] = s;
    }
}

__global__ void sigma_kernel(const float* __restrict__ style) {
    const int b = blockIdx.y;
    const int warp = threadIdx.x >> 5, lane = threadIdx.x & 31;
    const int oc = blockIdx.x * 8 + warp;
    float v = 0.f;
    for (int i = lane; i < NC; i += 32) {
        float s = style[b * NC + i];
        v += s * s * g_wsq[oc * NC + i];
    }
#pragma unroll
    for (int off = 16; off; off >>= 1) v += __shfl_xor_sync(0xffffffffu, v, off);
    if (lane == 0) g_sigma[b * NC + oc] = rsqrtf(v + EPSV);
}

// ---------------------------------------------------------------------------
// prep: weights -> fp16 tiles, layout [oc(128)][k(32)] packed 64B rows.
// grid (144, 4), 256 threads: thread = (oc 0..127) x (khalf 0..1)
// ---------------------------------------------------------------------------
__global__ void prep_b(const float* __restrict__ weight, float gain) {
    const int cc = blockIdx.x, octile = blockIdx.y;
    const int icch = cc / 9, tap = cc % 9;
    const int ocl = threadIdx.x >> 1;
    const int kh = (threadIdx.x & 1) * 16;
    const int oc = octile * 128 + ocl;
    const float* wr = weight + (size_t)oc * 4608 + (size_t)(icch * 32 + kh) * 9 + tap;
    union { __half2 h2[8]; uint4 u4[2]; } H;
#pragma unroll
    for (int j = 0; j < 8; ++j) {
        float v0 = wr[(2 * j) * 9] * gain;
        float v1 = wr[(2 * j + 1) * 9] * gain;
        H.h2[j] = __halves2half2(__float2half(v0), __float2half(v1));
    }
    unsigned char* blk = g_btiles + (size_t)(octile * NCHUNK + cc) * 8192;
    uint4* dh = (uint4*)(blk + ocl * 64 + kh * 2);
    dh[0] = H.u4[0]; dh[1] = H.u4[1];
}

// ---------------------------------------------------------------------------
// conv: grid (8 pixtiles, 4 octiles, 16 b), 256 threads (8 warps).
// CTA tile: M=128 oc x N=128 pix, K-chunk 32 (one tap), 144 chunks.
// X stored per ic-chunk as halo tile: 204 "pixel rows" (6 img rows x 34 cols,
// zero-padded) x 32 k halves, 80B row stride. Tap = address offset.
// smem: W0@0 W1@10240 | X0@20480 X1@36800 (16320 each) | sig@53120 sty@53632
// ---------------------------------------------------------------------------
#define RS 80u          // row stride bytes (40 halves)
#define WOFF(buf) ((uint32_t)(buf) * 10240u)
#define XOFF(buf) (20480u + (uint32_t)(buf) * 16320u)
#define SM_TOTAL 55680

__global__ void __launch_bounds__(256, 2)
conv_mma(const float* __restrict__ x, const float* __restrict__ style,
         float* __restrict__ out) {
    extern __shared__ char smem[];
    const uint32_t sb = smem_u32(smem);
    const int tid = threadIdx.x;
    const int lane = tid & 31, wid = tid >> 5;
    const int wm = wid & 1;        // m warp (oc): 0..1 -> offset wm*64
    const int wn = wid >> 1;       // n warp (pix row): 0..3
    const int pixtile = blockIdx.x, octile = blockIdx.y, b = blockIdx.z;

    float* s_sig = (float*)(smem + 53120);
    float* s_sty = (float*)(smem + 53632);
    for (int i = tid; i < 128; i += 256) s_sig[i] = g_sigma[b * NC + octile * 128 + i];
    for (int i = tid; i < NC; i += 256) s_sty[i] = style[b * NC + i];
    __syncthreads();

    const float* xb = x + (size_t)b * NC * HW2;
    const unsigned char* wbase = g_btiles + (size_t)octile * NCHUNK * 8192;

    // ---- X-build coords: thread t handles halo-tile pixel row t (0..203) ----
    const bool bact = tid < 204;
    const int blr = tid / 34;                 // local halo row 0..5
    const int bcc = tid % 34 - 1;             // image col -1..32
    const int bimgrow = pixtile * 4 - 1 + blr;
    const bool binimg = bact && ((unsigned)bimgrow < 32u) && ((unsigned)bcc < 32u);
    const float* xpix = xb + (binimg ? (bimgrow * 32 + bcc) : 0);

    // ldmatrix per-lane offsets
    const uint32_t aoff = (uint32_t)(lane & 15) * RS + (uint32_t)(lane >> 4) * 16u;
    // B lane base (kh=kw=0): halo row = (wn+1)*34 + n*8 + (lane&7) + 1
    uint32_t bb[4];
#pragma unroll
    for (int n = 0; n < 4; ++n)
        bb[n] = (uint32_t)(((wn + 1) * 34 + n * 8 + (lane & 7) + 1)) * RS +
                (uint32_t)((lane >> 3) & 1) * 16u;

    float acc[4][4][4];
#pragma unroll
    for (int m = 0; m < 4; ++m)
#pragma unroll
        for (int n = 0; n < 4; ++n)
#pragma unroll
            for (int r = 0; r < 4; ++r) acc[m][n][r] = 0.f;

    // ---- helpers ----
    auto issueW = [&](int c, uint32_t woff) {
        const unsigned char* src = wbase + (size_t)c * 8192;
#pragma unroll
        for (int j = 0; j < 2; ++j) {
            int cidx = tid + j * 256;               // 0..511 16B chunks
            int row = cidx >> 2, off = cidx & 3;
            CP_ASYNC16(sb + woff + row * RS + off * 16, src + cidx * 16);
        }
        CP_COMMIT();
    };
    // build 4 k-slices (kt*4 .. kt*4+3) of ic-chunk icch into X buffer xoff
    auto buildX4_ld = [&](int icch, int kt, float* v) {
#pragma unroll
        for (int j = 0; j < 4; ++j)
            v[j] = binimg ? xpix[(size_t)(icch * 32 + kt * 4 + j) << 10] : 0.f;
    };
    auto buildX4_st = [&](int icch, int kt, uint32_t xoff, const float* v) {
        if (!bact) return;
        union { __half2 h2[2]; uint2 u2; } P;
        const int styb = icch * 32 + kt * 4;
        P.h2[0] = __halves2half2(__float2half(v[0] * s_sty[styb + 0]),
                                 __float2half(v[1] * s_sty[styb + 1]));
        P.h2[1] = __halves2half2(__float2half(v[2] * s_sty[styb + 2]),
                                 __float2half(v[3] * s_sty[styb + 3]));
        *(uint2*)(smem + xoff + (uint32_t)tid * RS + kt * 8) = P.u2;
    };
    // one K=16 subtile of MMAs: W buffer woff, X buffer xoff, tap offset toff
    auto mmaKS = [&](uint32_t woff, uint32_t xoff, uint32_t toff, uint32_t kb) {
        uint32_t ah[4][4], bh[4][2];
#pragma unroll
        for (int m = 0; m < 4; ++m)
            LDMX4(ah[m], sb + woff + (uint32_t)(wm * 64 + m * 16) * RS + kb + aoff);
#pragma unroll
        for (int n = 0; n < 4; ++n)
            LDMX2(bh[n], sb + xoff + toff + bb[n] + kb);
#pragma unroll
        for (int m = 0; m < 4; ++m)
#pragma unroll
            for (int n = 0; n < 4; ++n) MMA16816(acc[m][n], ah[m], bh[n]);
    };

    // ---- prologue: build X chunk 0, load W chunk 0 ----
    {
#pragma unroll
        for (int kt = 0; kt < 8; ++kt) {
            float v[4];
            buildX4_ld(0, kt, v);
            buildX4_st(0, kt, XOFF(0), v);
        }
        issueW(0, WOFF(0));
        CP_WAIT0();
        __syncthreads();
    }

    // ---- main loop over 16 ic-chunks x 9 taps ----
#pragma unroll 1
    for (int icch = 0; icch < 16; ++icch) {
        const uint32_t xoff = XOFF(icch & 1);
        const uint32_t xnext = XOFF((icch & 1) ^ 1);
        const bool morex = (icch + 1 < 16);
#pragma unroll 1
        for (int tap = 0; tap < 9; ++tap) {
            const int c = icch * 9 + tap;
            const uint32_t woff = WOFF(c & 1);
            const bool morec = (c + 1 < NCHUNK);
            if (morec) issueW(c + 1, WOFF((c & 1) ^ 1));
            // tap -> address offset in halo tile
            const int kh = tap / 3 - 1, kw = tap % 3 - 1;
            const uint32_t toff = (uint32_t)((kh * 34 + kw) * (int)RS);
            float v[4];
            const bool bld = morex && tap < 8;
            if (bld) buildX4_ld(icch + 1, tap, v);     // LDG early (hidden)
            mmaKS(woff, xoff, toff, 0u);               // K subtile 0
            if (bld) buildX4_st(icch + 1, tap, xnext, v);
            mmaKS(woff, xoff, toff, 32u);              // K subtile 1
            if (morec) CP_WAIT0();
            __syncthreads();
        }
    }

    // ---- epilogue: demodulate + store ----
    float* ob = out + (size_t)b * NC * HW2 + (size_t)octile * 128 * HW2 +
                pixtile * 128;
#pragma unroll
    for (int m = 0; m < 4; ++m) {
        const int r0 = wm * 64 + m * 16 + (lane >> 2);
        const float sg0 = s_sig[r0], sg1 = s_sig[r0 + 8];
#pragma unroll
        for (int n = 0; n < 4; ++n) {
            const int col = wn * 32 + n * 8 + (lane & 3) * 2;
            float2 v0 = make_float2(acc[m][n][0] * sg0, acc[m][n][1] * sg0);
            float2 v1 = make_float2(acc[m][n][2] * sg1, acc[m][n][3] * sg1);
            *(float2*)(ob + (size_t)r0 * HW2 + col) = v0;
            *(float2*)(ob + (size_t)(r0 + 8) * HW2 + col) = v1;
        }
    }
}

// ---------------------------------------------------------------------------
extern "C" void kernel_launch(void* const* d_in, const int* in_sizes, int n_in,
                              void* d_out, int out_size) {
    const float* x      = (const float*)d_in[0];
    const float* style  = (const float*)d_in[1];
    const float* weight = (const float*)d_in[2];
    float* out          = (float*)d_out;
    (void)in_sizes; (void)n_in; (void)out_size;

    const float gain = 1.0f / sqrtf(4608.0f);

    cudaFuncSetAttribute(conv_mma, cudaFuncAttributeMaxDynamicSharedMemorySize,
                         SM_TOTAL);

    wsq_kernel<<<dim3(8, 64), 256>>>(weight, gain);
    prep_b<<<dim3(NCHUNK, 4), 256>>>(weight, gain);
    sigma_kernel<<<dim3(64, 16), 256>>>(style);
    conv_mma<<<dim3(8, 4, 16), 256, SM_TOTAL>>>(x, style, out);
}